// round 12
// baseline (speedup 1.0000x reference)
#include <cuda_runtime.h>
#include <cstdint>
#include <cstddef>

#define BB     8192
#define NNODE  17
#define CIN    256
#define COUT   256
#define NTOT   (BB * NNODE)                 // 139264
#define TBB    15
#define ROWS_V (TBB * NNODE)                // 255
#define NTILES ((BB + TBB - 1) / TBB)       // 547

// SMEM map
#define W_OFF      0                        // 4 mats x 32768
#define X_OFF      131072                   // 2 bufs x 40960 (hi@0, lo@20480, 80B rows)
#define XBUF_SZ    40960
#define PLANE_SZ   20480
#define MSH_OFF    212992
#define CDS_OFF    217344
#define BIAS_OFF   221696
#define OAS_OFF    221952
#define SMEM_BYTES 223232

__device__ float d_offA[NNODE * NNODE];
__device__ float d_Cdiag[NNODE * COUT];
// W^T: [g][mat][64n][256k] bf16, XOR-swizzled 512B rows; mat = w*2+(0:hi,1:lo)
__device__ __align__(16) unsigned short d_WT[4 * 4 * 64 * 256];
// X pre-converted: [row][plane(hi/lo)][256k] bf16  (1024B per row)
__device__ __align__(16) unsigned short d_Xbf[(size_t)NTOT * 512];

__device__ __forceinline__ uint32_t smem_u32(const void* p) {
    uint32_t a;
    asm("{ .reg .u64 t; cvta.to.shared.u64 t, %1; cvt.u32.u64 %0, t; }" : "=r"(a) : "l"(p));
    return a;
}
__device__ __forceinline__ void ldsm4(uint32_t* r, uint32_t a) {
    asm volatile("ldmatrix.sync.aligned.m8n8.x4.shared.b16 {%0,%1,%2,%3}, [%4];"
                 : "=r"(r[0]), "=r"(r[1]), "=r"(r[2]), "=r"(r[3]) : "r"(a));
}
#define MMA_BF16(ac, A, b0, b1) \
    asm volatile("mma.sync.aligned.m16n8k16.row.col.f32.bf16.bf16.f32 " \
        "{%0,%1,%2,%3}, {%4,%5,%6,%7}, {%8,%9}, {%0,%1,%2,%3};" \
        : "+f"((ac)[0]), "+f"((ac)[1]), "+f"((ac)[2]), "+f"((ac)[3]) \
        : "r"((A)[0]), "r"((A)[1]), "r"((A)[2]), "r"((A)[3]), "r"(b0), "r"(b1))
__device__ __forceinline__ void cp16(uint32_t d, const void* s) {
    asm volatile("cp.async.cg.shared.global [%0], [%1], 16;" :: "r"(d), "l"(s));
}
__device__ __forceinline__ void cp16z(uint32_t d, const void* s, int sz) {
    asm volatile("cp.async.cg.shared.global [%0], [%1], 16, %2;" :: "r"(d), "l"(s), "r"(sz));
}
#define CP_COMMIT() asm volatile("cp.async.commit_group;" ::: "memory")
#define CP_WAIT0()  asm volatile("cp.async.wait_group 0;" ::: "memory")

__device__ __forceinline__ void split4(float4 v, uint2& hi, uint2& lo) {
    uint32_t h0, h1, l0, l1;
    asm("cvt.rn.bf16x2.f32 %0, %1, %2;" : "=r"(h0) : "f"(v.y), "f"(v.x));
    asm("cvt.rn.bf16x2.f32 %0, %1, %2;" : "=r"(h1) : "f"(v.w), "f"(v.z));
    float hx = __uint_as_float(h0 << 16), hy = __uint_as_float(h0 & 0xFFFF0000u);
    float hz = __uint_as_float(h1 << 16), hw = __uint_as_float(h1 & 0xFFFF0000u);
    asm("cvt.rn.bf16x2.f32 %0, %1, %2;" : "=r"(l0) : "f"(v.y - hy), "f"(v.x - hx));
    asm("cvt.rn.bf16x2.f32 %0, %1, %2;" : "=r"(l1) : "f"(v.w - hw), "f"(v.z - hz));
    hi = make_uint2(h0, h1); lo = make_uint2(l0, l1);
}

// ---------------- prep: A tables + W pack ----------------
__global__ void prep_all(const float* __restrict__ W, const float* __restrict__ M,
                         const float* __restrict__ adj, const float* __restrict__ adj2) {
    int t = threadIdx.x;
    if (blockIdx.x == 0) {
        __shared__ float As[NNODE * NNODE];
        for (int idx = t; idx < NNODE * NNODE; idx += 256) {
            int i = idx / NNODE, j = idx % NNODE;
            As[idx] = 0.5f * (adj[i*NNODE+j] + adj2[i*NNODE+j] + adj[j*NNODE+i] + adj2[j*NNODE+i]);
        }
        __syncthreads();
        for (int idx = t; idx < NNODE * NNODE; idx += 256) {
            int i = idx / NNODE, j = idx % NNODE;
            d_offA[idx] = (i == j) ? 0.0f : As[idx];
        }
        for (int idx = t; idx < NNODE * COUT; idx += 256)
            d_Cdiag[idx] = As[(idx >> 8) * NNODE + (idx >> 8)] * M[idx];
    }
    for (int idx = blockIdx.x * 256 + t; idx < 2 * CIN * COUT; idx += gridDim.x * 256) {
        int w = idx >> 16, k = (idx >> 8) & 255, n = idx & 255;
        float v = W[w * CIN * COUT + k * COUT + n];
        unsigned short hb, lb;
        asm("cvt.rn.bf16.f32 %0, %1;" : "=h"(hb) : "f"(v));
        float hf = __uint_as_float(((unsigned)hb) << 16);
        asm("cvt.rn.bf16.f32 %0, %1;" : "=h"(lb) : "f"(v - hf));
        int g = n >> 6, nl = n & 63;
        unsigned byte = (unsigned)(nl * 512 + ((k * 2) ^ ((nl & 7) << 4)));
        unsigned bh = (unsigned)(g * 4 + w * 2) * 16384u;
        d_WT[bh + (byte >> 1)] = hb;
        d_WT[bh + 16384 + (byte >> 1)] = lb;
    }
}

// ---------------- prep: X -> bf16 hi/lo planes ----------------
__global__ void prep_x(const float* __restrict__ x) {
    const float4* x4 = (const float4*)x;
    for (size_t i = (size_t)blockIdx.x * 256 + threadIdx.x; i < (size_t)NTOT * 64;
         i += (size_t)gridDim.x * 256) {
        uint2 hi, lo;
        split4(x4[i], hi, lo);
        size_t row = i >> 6, q = i & 63;
        *(uint2*)(d_Xbf + row * 512 + q * 4) = hi;
        *(uint2*)(d_Xbf + row * 512 + 256 + q * 4) = lo;
    }
}

// ---------------- mma step: 3 passes over 64x32 warp tile ----------------
__device__ __forceinline__ void mma_step(float (&acc)[2][4][4][4], uint32_t aB, uint32_t bB) {
    uint32_t A0[4][4], A1[4][4], Bm[2][2][4];
#pragma unroll
    for (int mt = 0; mt < 4; mt++) ldsm4(A0[mt], aB + mt * 1280);
#pragma unroll
    for (int mt = 0; mt < 4; mt++) ldsm4(A1[mt], aB + PLANE_SZ + mt * 1280);
#pragma unroll
    for (int w2 = 0; w2 < 2; w2++)
#pragma unroll
        for (int p = 0; p < 2; p++) ldsm4(Bm[w2][p], bB + (uint32_t)(w2*2)*32768u + (uint32_t)p*8192u);
#pragma unroll
    for (int w2 = 0; w2 < 2; w2++)
#pragma unroll
        for (int mt = 0; mt < 4; mt++)
#pragma unroll
            for (int nt = 0; nt < 4; nt++) {
                int p = nt >> 1, o = (nt & 1) * 2;
                MMA_BF16(acc[w2][mt][nt], A0[mt], Bm[w2][p][o], Bm[w2][p][o+1]);
            }
#pragma unroll
    for (int w2 = 0; w2 < 2; w2++)
#pragma unroll
        for (int mt = 0; mt < 4; mt++)
#pragma unroll
            for (int nt = 0; nt < 4; nt++) {
                int p = nt >> 1, o = (nt & 1) * 2;
                MMA_BF16(acc[w2][mt][nt], A1[mt], Bm[w2][p][o], Bm[w2][p][o+1]);
            }
#pragma unroll
    for (int w2 = 0; w2 < 2; w2++)
#pragma unroll
        for (int p = 0; p < 2; p++) ldsm4(Bm[w2][p], bB + (uint32_t)(w2*2+1)*32768u + (uint32_t)p*8192u);
#pragma unroll
    for (int w2 = 0; w2 < 2; w2++)
#pragma unroll
        for (int mt = 0; mt < 4; mt++)
#pragma unroll
            for (int nt = 0; nt < 4; nt++) {
                int p = nt >> 1, o = (nt & 1) * 2;
                MMA_BF16(acc[w2][mt][nt], A0[mt], Bm[w2][p][o], Bm[w2][p][o+1]);
            }
}

// load one k32 chunk of X (both planes) into an 80B-stride smem buffer
__device__ __forceinline__ void issue_x(uint32_t smX, int row0, int valid, int c, int t) {
    const char* gX = (const char*)d_Xbf;
#pragma unroll
    for (int j = 0; j < 8; j++) {
        int slot = t + j * 256;                    // 2048 slots = 256 rows x 2 planes x 4
        int r = slot >> 3, p = (slot >> 2) & 1, u = slot & 3;
        int gr = (r < valid) ? (row0 + r) : row0;
        cp16z(smX + (uint32_t)p * PLANE_SZ + (uint32_t)r * 80u + (uint32_t)u * 16u,
              gX + (size_t)gr * 1024 + p * 512 + c * 64 + u * 16, (r < valid) ? 16 : 0);
    }
}

// ---------------- main ----------------
__global__ void __launch_bounds__(256, 1)
mgc_hmma(const float* __restrict__ M, const float* __restrict__ bias, float* __restrict__ out) {
    extern __shared__ char smc[];
    const uint32_t smb = smem_u32(smc);
    const int t = threadIdx.x, wid = t >> 5, lid = t & 31;
    const int g = blockIdx.x & 3, tl = blockIdx.x >> 2;
    const int warp_m = wid & 3, warp_n = wid >> 2;
    const int row0 = tl * ROWS_V;
    const int valid = min(ROWS_V, NTOT - row0);
    const int nb = valid / NNODE;

    // prologue cp group: W slice + X chunk 0
    {
        const char* wsrc = (const char*)d_WT + (size_t)g * 131072;
        for (int i = 0; i < 32; i++) {
            int idx = t + i * 256;
            cp16(smb + W_OFF + (uint32_t)idx * 16, wsrc + (size_t)idx * 16);
        }
        issue_x(smb + X_OFF, row0, valid, 0, t);
        CP_COMMIT();
    }
    // tables
    float* Msh = (float*)(smc + MSH_OFF);
    float* Cds = (float*)(smc + CDS_OFF);
    float* bss = (float*)(smc + BIAS_OFF);
    float* oAs = (float*)(smc + OAS_OFF);
    for (int idx = t; idx < NNODE * 64; idx += 256) {
        int i = idx >> 6, dl = idx & 63;
        Msh[idx] = M[i * COUT + g * 64 + dl];
        Cds[idx] = d_Cdiag[i * COUT + g * 64 + dl];
    }
    if (t < 64) bss[t] = bias[g * 64 + t];
    for (int idx = t; idx < NNODE * NNODE; idx += 256) oAs[idx] = d_offA[idx];

    // lane addressing
    const uint32_t lxor = (uint32_t)(lid & 7) << 4;
    const uint32_t aLane = (uint32_t)warp_m * 5120u + (uint32_t)(lid & 15) * 80u + (uint32_t)(lid >> 4) * 16u;
    const uint32_t bKx = (uint32_t)((lid >> 3) & 1) * 16u;
    const uint32_t bBase0 = smb + W_OFF + (uint32_t)(warp_n * 32 + (lid >> 4) * 8 + (lid & 7)) * 512u;

    float acc[2][4][4][4];
#pragma unroll
    for (int a = 0; a < 2; a++)
#pragma unroll
        for (int b = 0; b < 4; b++)
#pragma unroll
            for (int c = 0; c < 4; c++)
#pragma unroll
                for (int d = 0; d < 4; d++) acc[a][b][c][d] = 0.f;

    // K mainloop: 8 chunks of k32, double-buffered
    for (int c = 0; c < 8; c++) {
        CP_WAIT0();
        __syncthreads();
        if (c < 7) { issue_x(smb + X_OFF + (uint32_t)((c + 1) & 1) * XBUF_SZ, row0, valid, c + 1, t); CP_COMMIT(); }
        const uint32_t aB = smb + X_OFF + (uint32_t)(c & 1) * XBUF_SZ + aLane;
        mma_step(acc, aB,      bBase0 + (((uint32_t)c * 64u + bKx) ^ lxor));
        mma_step(acc, aB + 32, bBase0 + (((uint32_t)c * 64u + 32u + bKx) ^ lxor));
    }
    __syncthreads();

    // epilogue: 2 phases (<=8 b's each), staging overlays X buffers
    float4* PS = (float4*)(smc + X_OFF);
#pragma unroll 1
    for (int ph = 0; ph < 2; ph++) {
        const int bstart = ph * 8;
        const int nbp = min(nb - bstart, 8 - ph);
        if (nbp <= 0) break;
        const int lo = bstart * NNODE, cnt = nbp * NNODE;
        // stage float4 {Cd*h0+bias (x2), M*h1 (x2)} per (row, colpair)
#pragma unroll
        for (int mt = 0; mt < 4; mt++)
#pragma unroll
            for (int rh = 0; rh < 2; rh++) {
                const int r = warp_m * 64 + mt * 16 + rh * 8 + (lid >> 2);
                const int rr = r - lo;
                if (rr >= 0 && rr < cnt) {
                    const int i = r % NNODE;
#pragma unroll
                    for (int nt = 0; nt < 4; nt++) {
                        const int col = warp_n * 32 + nt * 8 + (lid & 3) * 2;
                        float2 mv = *(const float2*)(Msh + i * 64 + col);
                        float2 cd = *(const float2*)(Cds + i * 64 + col);
                        float2 bv = *(const float2*)(bss + col);
                        float4 st;
                        st.x = fmaf(cd.x, acc[0][mt][nt][rh*2+0], bv.x);
                        st.y = fmaf(cd.y, acc[0][mt][nt][rh*2+1], bv.y);
                        st.z = mv.x * acc[1][mt][nt][rh*2+0];
                        st.w = mv.y * acc[1][mt][nt][rh*2+1];
                        PS[rr * 33 + (col >> 1)] = st;
                    }
                }
            }
        __syncthreads();
        // aggregate: thread -> (b, colpair); each staged row read once
        if (t < nbp * 32) {
            const int bl = t >> 5, cp = t & 31;
            float2 res[NNODE];
#pragma unroll
            for (int i = 0; i < NNODE; i++) res[i] = make_float2(0.f, 0.f);
            const float4* base = PS + bl * NNODE * 33 + cp;
#pragma unroll 1
            for (int j = 0; j < NNODE; j++) {
                float4 s = base[j * 33];
                res[j].x += s.x; res[j].y += s.y;
#pragma unroll
                for (int i = 0; i < NNODE; i++) {
                    float a = oAs[j * NNODE + i];
                    res[i].x = fmaf(a, s.z, res[i].x);
                    res[i].y = fmaf(a, s.w, res[i].y);
                }
            }
#pragma unroll 1
            for (int j = 0; j < NNODE; j++)
                *(float2*)(out + (size_t)(row0 + (bstart + bl) * NNODE + j) * COUT + g * 64 + cp * 2) = res[j];
        }
        __syncthreads();
    }
}

// ---------------------------------------------------------------------------
extern "C" void kernel_launch(void* const* d_in, const int* in_sizes, int n_in,
                              void* d_out, int out_size) {
    const float* x    = (const float*)d_in[0];
    const float* W    = (const float*)d_in[1];
    const float* M    = (const float*)d_in[2];
    const float* adj  = (const float*)d_in[3];
    const float* adj2 = (const float*)d_in[4];
    const float* bias = (const float*)d_in[5];
    float* out = (float*)d_out;

    static bool attr_set = false;
    if (!attr_set) {
        cudaFuncSetAttribute(mgc_hmma, cudaFuncAttributeMaxDynamicSharedMemorySize, SMEM_BYTES);
        attr_set = true;
    }
    prep_all<<<128, 256>>>(W, M, adj, adj2);
    prep_x<<<4096, 256>>>(x);
    mgc_hmma<<<NTILES * 4, 256, SMEM_BYTES>>>(M, bias, out);
}

// round 14
// speedup vs baseline: 1.0567x; 1.0567x over previous
#include <cuda_runtime.h>
#include <cstdint>
#include <cstddef>

#define BB     8192
#define NNODE  17
#define CIN    256
#define COUT   256
#define NTOT   (BB * NNODE)                 // 139264
#define TBB    7
#define ROWS_T (TBB * NNODE)                // 119
#define NTILES ((BB + TBB - 1) / TBB)       // 1171

// SMEM map
#define W_OFF      0                        // 4 mats x 32768
#define X_OFF      131072                   // 2 bufs x 20480 (hi@0, lo@10240, 80B rows)
#define XBUF_SZ    20480
#define PLANE_SZ   10240
#define PS_OFF     172032                   // 68 rows x 33 float4 = 35904
#define MSH_OFF    207936
#define CDS_OFF    212288
#define BIAS_OFF   216640
#define OAS_OFF    216896
#define SMEM_BYTES 218112

__device__ float d_offA[NNODE * NNODE];
__device__ float d_Cdiag[NNODE * COUT];
// W^T: [g][mat][64n][256k] bf16, XOR-swizzled 512B rows; mat = w*2+(0:hi,1:lo)
__device__ __align__(16) unsigned short d_WT[4 * 4 * 64 * 256];
// X pre-converted: [row][plane hi/lo][256k] bf16 (1024B per row)
__device__ __align__(16) unsigned short d_Xbf[(size_t)NTOT * 512];

__device__ __forceinline__ uint32_t smem_u32(const void* p) {
    uint32_t a;
    asm("{ .reg .u64 t; cvta.to.shared.u64 t, %1; cvt.u32.u64 %0, t; }" : "=r"(a) : "l"(p));
    return a;
}
__device__ __forceinline__ void ldsm4(uint32_t* r, uint32_t a) {
    asm volatile("ldmatrix.sync.aligned.m8n8.x4.shared.b16 {%0,%1,%2,%3}, [%4];"
                 : "=r"(r[0]), "=r"(r[1]), "=r"(r[2]), "=r"(r[3]) : "r"(a));
}
#define MMA_BF16(ac, A, b0, b1) \
    asm volatile("mma.sync.aligned.m16n8k16.row.col.f32.bf16.bf16.f32 " \
        "{%0,%1,%2,%3}, {%4,%5,%6,%7}, {%8,%9}, {%0,%1,%2,%3};" \
        : "+f"((ac)[0]), "+f"((ac)[1]), "+f"((ac)[2]), "+f"((ac)[3]) \
        : "r"((A)[0]), "r"((A)[1]), "r"((A)[2]), "r"((A)[3]), "r"(b0), "r"(b1))
__device__ __forceinline__ void cp16(uint32_t d, const void* s) {
    asm volatile("cp.async.cg.shared.global [%0], [%1], 16;" :: "r"(d), "l"(s));
}
__device__ __forceinline__ void cp16z(uint32_t d, const void* s, int sz) {
    asm volatile("cp.async.cg.shared.global [%0], [%1], 16, %2;" :: "r"(d), "l"(s), "r"(sz));
}
#define CP_COMMIT() asm volatile("cp.async.commit_group;" ::: "memory")
#define CP_WAIT0()  asm volatile("cp.async.wait_group 0;" ::: "memory")

__device__ __forceinline__ void split4(float4 v, uint2& hi, uint2& lo) {
    uint32_t h0, h1, l0, l1;
    asm("cvt.rn.bf16x2.f32 %0, %1, %2;" : "=r"(h0) : "f"(v.y), "f"(v.x));
    asm("cvt.rn.bf16x2.f32 %0, %1, %2;" : "=r"(h1) : "f"(v.w), "f"(v.z));
    float hx = __uint_as_float(h0 << 16), hy = __uint_as_float(h0 & 0xFFFF0000u);
    float hz = __uint_as_float(h1 << 16), hw = __uint_as_float(h1 & 0xFFFF0000u);
    asm("cvt.rn.bf16x2.f32 %0, %1, %2;" : "=r"(l0) : "f"(v.y - hy), "f"(v.x - hx));
    asm("cvt.rn.bf16x2.f32 %0, %1, %2;" : "=r"(l1) : "f"(v.w - hw), "f"(v.z - hz));
    hi = make_uint2(h0, h1); lo = make_uint2(l0, l1);
}

// ---------------- merged prep: blocks [0,128) = tables + W pack; rest = X split
__global__ void prep(const float* __restrict__ x, const float* __restrict__ W,
                     const float* __restrict__ M,
                     const float* __restrict__ adj, const float* __restrict__ adj2) {
    const int t = threadIdx.x;
    if (blockIdx.x < 128) {
        if (blockIdx.x == 0) {
            __shared__ float As[NNODE * NNODE];
            for (int idx = t; idx < NNODE * NNODE; idx += 256) {
                int i = idx / NNODE, j = idx % NNODE;
                As[idx] = 0.5f * (adj[i*NNODE+j] + adj2[i*NNODE+j] + adj[j*NNODE+i] + adj2[j*NNODE+i]);
            }
            __syncthreads();
            for (int idx = t; idx < NNODE * NNODE; idx += 256) {
                int i = idx / NNODE, j = idx % NNODE;
                d_offA[idx] = (i == j) ? 0.0f : As[idx];
            }
            for (int idx = t; idx < NNODE * COUT; idx += 256)
                d_Cdiag[idx] = As[(idx >> 8) * NNODE + (idx >> 8)] * M[idx];
        }
        for (int idx = blockIdx.x * 256 + t; idx < 2 * CIN * COUT; idx += 128 * 256) {
            int w = idx >> 16, k = (idx >> 8) & 255, n = idx & 255;
            float v = W[w * CIN * COUT + k * COUT + n];
            unsigned short hb, lb;
            asm("cvt.rn.bf16.f32 %0, %1;" : "=h"(hb) : "f"(v));
            float hf = __uint_as_float(((unsigned)hb) << 16);
            asm("cvt.rn.bf16.f32 %0, %1;" : "=h"(lb) : "f"(v - hf));
            int g = n >> 6, nl = n & 63;
            unsigned byte = (unsigned)(nl * 512 + ((k * 2) ^ ((nl & 7) << 4)));
            unsigned bh = (unsigned)(g * 4 + w * 2) * 16384u;
            d_WT[bh + (byte >> 1)] = hb;
            d_WT[bh + 16384 + (byte >> 1)] = lb;
        }
    } else {
        const float4* x4 = (const float4*)x;
        for (size_t i = (size_t)(blockIdx.x - 128) * 256 + t; i < (size_t)NTOT * 64;
             i += (size_t)(gridDim.x - 128) * 256) {
            uint2 hi, lo;
            split4(x4[i], hi, lo);
            size_t row = i >> 6, q = i & 63;
            *(uint2*)(d_Xbf + row * 512 + q * 4) = hi;
            *(uint2*)(d_Xbf + row * 512 + 256 + q * 4) = lo;
        }
    }
}

// ---------------- mma step: 32x32 warp tile, both GEMMs, 3 passes ----------
__device__ __forceinline__ void mma_step(float (&acc)[2][2][4][4], uint32_t aB, uint32_t bB) {
    uint32_t A0[2][4], A1[2][4], Bm[2][2][4];
#pragma unroll
    for (int mt = 0; mt < 2; mt++) ldsm4(A0[mt], aB + mt * 1280);
#pragma unroll
    for (int mt = 0; mt < 2; mt++) ldsm4(A1[mt], aB + PLANE_SZ + mt * 1280);
#pragma unroll
    for (int w2 = 0; w2 < 2; w2++)
#pragma unroll
        for (int p = 0; p < 2; p++) ldsm4(Bm[w2][p], bB + (uint32_t)(w2*2)*32768u + (uint32_t)p*8192u);
    // pass 0: xhi * Whi
#pragma unroll
    for (int w2 = 0; w2 < 2; w2++)
#pragma unroll
        for (int mt = 0; mt < 2; mt++)
#pragma unroll
            for (int nt = 0; nt < 4; nt++) {
                int p = nt >> 1, o = (nt & 1) * 2;
                MMA_BF16(acc[w2][mt][nt], A0[mt], Bm[w2][p][o], Bm[w2][p][o+1]);
            }
    // pass 1: xlo * Whi
#pragma unroll
    for (int w2 = 0; w2 < 2; w2++)
#pragma unroll
        for (int mt = 0; mt < 2; mt++)
#pragma unroll
            for (int nt = 0; nt < 4; nt++) {
                int p = nt >> 1, o = (nt & 1) * 2;
                MMA_BF16(acc[w2][mt][nt], A1[mt], Bm[w2][p][o], Bm[w2][p][o+1]);
            }
    // reload B lo-mats, pass 2: xhi * Wlo
#pragma unroll
    for (int w2 = 0; w2 < 2; w2++)
#pragma unroll
        for (int p = 0; p < 2; p++) ldsm4(Bm[w2][p], bB + (uint32_t)(w2*2+1)*32768u + (uint32_t)p*8192u);
#pragma unroll
    for (int w2 = 0; w2 < 2; w2++)
#pragma unroll
        for (int mt = 0; mt < 2; mt++)
#pragma unroll
            for (int nt = 0; nt < 4; nt++) {
                int p = nt >> 1, o = (nt & 1) * 2;
                MMA_BF16(acc[w2][mt][nt], A0[mt], Bm[w2][p][o], Bm[w2][p][o+1]);
            }
}

// load one k32 chunk (both planes) of rows [row0, row0+128) into 80B-stride buf
__device__ __forceinline__ void issue_x(uint32_t smX, int row0, int valid, int c, int t) {
    const char* gX = (const char*)d_Xbf;
#pragma unroll
    for (int j = 0; j < 4; j++) {
        int slot = t + j * 256;                 // 1024 slots = 128 rows x 2 planes x 4
        int r = slot >> 3, p = (slot >> 2) & 1, u = slot & 3;
        int gr = (r < valid) ? (row0 + r) : row0;
        cp16z(smX + (uint32_t)p * PLANE_SZ + (uint32_t)r * 80u + (uint32_t)u * 16u,
              gX + (size_t)gr * 1024 + p * 512 + c * 64 + u * 16, (r < valid) ? 16 : 0);
    }
}

// ---------------- main ----------------
__global__ void __launch_bounds__(256, 1)
mgc_hmma(const float* __restrict__ M, const float* __restrict__ bias, float* __restrict__ out) {
    extern __shared__ char smc[];
    const uint32_t smb = smem_u32(smc);
    const int t = threadIdx.x, wid = t >> 5, lid = t & 31;
    const int g = blockIdx.x & 3, sidx = blockIdx.x >> 2;
    const int warp_m = wid & 3, warp_n = wid >> 2;

    // prologue cp group: resident W slice + first tile's X chunk 0
    {
        const char* wsrc = (const char*)d_WT + (size_t)g * 131072;
        for (int i = 0; i < 32; i++) {
            int idx = t + i * 256;
            cp16(smb + W_OFF + (uint32_t)idx * 16, wsrc + (size_t)idx * 16);
        }
        int row0 = sidx * ROWS_T;
        issue_x(smb + X_OFF, row0, min(ROWS_T, NTOT - row0), 0, t);
        CP_COMMIT();
    }
    // tables
    float* Msh = (float*)(smc + MSH_OFF);
    float* Cds = (float*)(smc + CDS_OFF);
    float* bss = (float*)(smc + BIAS_OFF);
    float* oAs = (float*)(smc + OAS_OFF);
    for (int idx = t; idx < NNODE * 64; idx += 256) {
        int i = idx >> 6, dl = idx & 63;
        Msh[idx] = M[i * COUT + g * 64 + dl];
        Cds[idx] = d_Cdiag[i * COUT + g * 64 + dl];
    }
    if (t < 64) bss[t] = bias[g * 64 + t];
    for (int idx = t; idx < NNODE * NNODE; idx += 256) oAs[idx] = d_offA[idx];

    // lane addressing
    const uint32_t lxor  = (uint32_t)(lid & 7) << 4;
    const uint32_t aLane = (uint32_t)warp_m * 2560u + (uint32_t)(lid & 15) * 80u + (uint32_t)(lid >> 4) * 16u;
    const uint32_t bKx   = (uint32_t)((lid >> 3) & 1) * 16u;
    const uint32_t bBase0 = smb + W_OFF + (uint32_t)(warp_n * 32 + (lid >> 4) * 8 + (lid & 7)) * 512u;

    float4* PS = (float4*)(smc + PS_OFF);

    for (int tl = sidx; tl < NTILES; tl += 148) {
        const int row0  = tl * ROWS_T;
        const int valid = min(ROWS_T, NTOT - row0);
        const int nb    = valid / NNODE;

        float acc[2][2][4][4];
#pragma unroll
        for (int a = 0; a < 2; a++)
#pragma unroll
            for (int b = 0; b < 2; b++)
#pragma unroll
                for (int c = 0; c < 4; c++)
#pragma unroll
                    for (int d = 0; d < 4; d++) acc[a][b][c][d] = 0.f;

        // K mainloop: 8 chunks of k32, double-buffered
        for (int c = 0; c < 8; c++) {
            CP_WAIT0();
            __syncthreads();
            if (c < 7) {
                issue_x(smb + X_OFF + (uint32_t)((c + 1) & 1) * XBUF_SZ, row0, valid, c + 1, t);
                CP_COMMIT();
            } else {
                int tn = tl + 148;
                if (tn < NTILES) {   // prefetch next tile's chunk 0 into buf 0
                    int nrow0 = tn * ROWS_T;
                    issue_x(smb + X_OFF, nrow0, min(ROWS_T, NTOT - nrow0), 0, t);
                    CP_COMMIT();
                }
            }
            const uint32_t aB = smb + X_OFF + (uint32_t)(c & 1) * XBUF_SZ + aLane;
            mma_step(acc, aB,      bBase0 + (((uint32_t)c * 64u + bKx) ^ lxor));
            mma_step(acc, aB + 32, bBase0 + (((uint32_t)c * 64u + 32u + bKx) ^ lxor));
        }
        __syncthreads();

        // epilogue: 2 phases of <=4 b's; staging region is independent of X bufs
#pragma unroll 1
        for (int ph = 0; ph < 2; ph++) {
            const int bstart = ph * 4;
            const int nbp = min(nb - bstart, 4);
            if (nbp <= 0) break;
            const int lo = bstart * NNODE, cnt = nbp * NNODE;
            // stage float4 {Cd*h0+bias (x2), M*h1 (x2)}
#pragma unroll
            for (int mt = 0; mt < 2; mt++)
#pragma unroll
                for (int rh = 0; rh < 2; rh++) {
                    const int r = warp_m * 32 + mt * 16 + rh * 8 + (lid >> 2);
                    const int rr = r - lo;
                    if (rr >= 0 && rr < cnt) {
                        const int i = r % NNODE;
#pragma unroll
                        for (int nt = 0; nt < 4; nt++) {
                            const int col = warp_n * 32 + nt * 8 + (lid & 3) * 2;
                            float2 mv = *(const float2*)(Msh + i * 64 + col);
                            float2 cd = *(const float2*)(Cds + i * 64 + col);
                            float2 bv = *(const float2*)(bss + col);
                            float4 st;
                            st.x = fmaf(cd.x, acc[0][mt][nt][rh*2+0], bv.x);
                            st.y = fmaf(cd.y, acc[0][mt][nt][rh*2+1], bv.y);
                            st.z = mv.x * acc[1][mt][nt][rh*2+0];
                            st.w = mv.y * acc[1][mt][nt][rh*2+1];
                            PS[rr * 33 + (col >> 1)] = st;
                        }
                    }
                }
            __syncthreads();
            // aggregate: thread -> (b, colpair); each staged row read once
            if (t < nbp * 32) {
                const int bl = t >> 5, cp = t & 31;
                float2 res[NNODE];
#pragma unroll
                for (int i = 0; i < NNODE; i++) res[i] = make_float2(0.f, 0.f);
                const float4* base = PS + bl * NNODE * 33 + cp;
#pragma unroll 1
                for (int j = 0; j < NNODE; j++) {
                    float4 s = base[j * 33];
                    res[j].x += s.x; res[j].y += s.y;
#pragma unroll
                    for (int i = 0; i < NNODE; i++) {
                        float a = oAs[j * NNODE + i];
                        res[i].x = fmaf(a, s.z, res[i].x);
                        res[i].y = fmaf(a, s.w, res[i].y);
                    }
                }
#pragma unroll 1
                for (int j = 0; j < NNODE; j++)
                    *(float2*)(out + (size_t)(row0 + (bstart + bl) * NNODE + j) * COUT + g * 64 + cp * 2) = res[j];
            }
            __syncthreads();
        }
    }
}

// ---------------------------------------------------------------------------
extern "C" void kernel_launch(void* const* d_in, const int* in_sizes, int n_in,
                              void* d_out, int out_size) {
    const float* x    = (const float*)d_in[0];
    const float* W    = (const float*)d_in[1];
    const float* M    = (const float*)d_in[2];
    const float* adj  = (const float*)d_in[3];
    const float* adj2 = (const float*)d_in[4];
    const float* bias = (const float*)d_in[5];
    float* out = (float*)d_out;

    static bool attr_set = false;
    if (!attr_set) {
        cudaFuncSetAttribute(mgc_hmma, cudaFuncAttributeMaxDynamicSharedMemorySize, SMEM_BYTES);
        attr_set = true;
    }
    prep<<<4224, 256>>>(x, W, M, adj, adj2);
    mgc_hmma<<<592, 256, SMEM_BYTES>>>(M, bias, out);
}